// round 2
// baseline (speedup 1.0000x reference)
#include <cuda_runtime.h>

#define KPT 17
#define LOG2E 1.4426950408889634f

// cc[k] = -LOG2E / (2 * var_k * area), var_k = (2*sigma_k)^2, sigma_k = S_k/10
// => base = -12.5 * LOG2E / S_k^2
#define CB(s) (-12.5f * LOG2E / ((s) * (s)))
__constant__ float c_cbase[KPT] = {
    CB(0.26f), CB(0.25f), CB(0.25f), CB(0.35f), CB(0.35f),
    CB(0.79f), CB(0.79f), CB(0.72f), CB(0.72f),
    CB(0.62f), CB(0.62f), CB(1.07f), CB(1.07f),
    CB(0.87f), CB(0.87f), CB(0.89f), CB(0.89f)
};

__device__ __forceinline__ float cls_cost_for(const float* __restrict__ logits,
                                              int n, int c) {
    // softmax over 2 classes, then focal-style pos - neg cost at class c
    float a = logits[2 * n + 0];
    float b = logits[2 * n + 1];
    float m = fmaxf(a, b);
    float e0 = expf(a - m), e1 = expf(b - m);
    float p = ((c == 0) ? e0 : e1) / (e0 + e1);
    float omp = 1.0f - p;
    float pos = -logf(p + 1e-12f) * 0.25f * omp * omp;
    float neg = -logf(omp + 1e-12f) * 0.75f * p * p;
    return pos - neg;
}

extern "C" __global__ void __launch_bounds__(256)
matcher_kernel(const float* __restrict__ logits,   // [N, 2]
               const float* __restrict__ pkpt,     // [N, 2*K]
               const int* __restrict__ tids,       // [G] (int32 on device)
               const float* __restrict__ areas,    // [G]
               const float* __restrict__ gkpt,     // [G, 3*K]
               float* __restrict__ out,            // [N, G]
               int N, int G, int rows_per_block)
{
    const int g   = threadIdx.x;   // one target per thread, blockDim.x == G
    const int tid = threadIdx.x;

    __shared__ float s_pred[2][2 * KPT];
    __shared__ float s_cls[2][2];

    // --- per-thread (per-target) constants: registers for the whole block ---
    float gx[KPT], gy[KPT], cc[KPT];
    float inv_area = 1.0f / areas[g];
    int   cid = tids[g];
    cid = (cid < 0) ? 0 : ((cid > 1) ? 1 : cid);
    #pragma unroll
    for (int k = 0; k < KPT; ++k) {
        gx[k] = gkpt[g * 3 * KPT + 3 * k + 0];
        gy[k] = gkpt[g * 3 * KPT + 3 * k + 1];
        cc[k] = c_cbase[k] * inv_area;   // ex2 arg multiplier (negative)
    }

    int ns = blockIdx.x * rows_per_block;
    int ne = min(ns + rows_per_block, N);
    if (ns >= ne) return;

    // --- preload first n into buffer 0 ---
    {
        int n = ns;
        if (tid < 2 * KPT) s_pred[0][tid] = pkpt[n * 2 * KPT + tid];
        if (tid >= 64 && tid < 66) s_cls[0][tid - 64] = cls_cost_for(logits, n, tid - 64);
    }
    __syncthreads();

    int buf = 0;
    for (int n = ns; n < ne; ++n) {
        const int nb = buf;
        // prefetch next row into the other buffer
        const int nn = n + 1;
        if (nn < ne) {
            const int wb = buf ^ 1;
            if (tid < 2 * KPT) s_pred[wb][tid] = pkpt[nn * 2 * KPT + tid];
            if (tid >= 64 && tid < 66) s_cls[wb][tid - 64] = cls_cost_for(logits, nn, tid - 64);
        }

        float l1 = 0.0f, oks = 0.0f;
        #pragma unroll
        for (int k = 0; k < KPT; ++k) {
            float px = s_pred[nb][2 * k];      // LDS broadcast (conflict-free)
            float py = s_pred[nb][2 * k + 1];
            float dx = px - gx[k];
            float dy = py - gy[k];
            l1 += fabsf(dx);
            l1 += fabsf(dy);
            float d2 = fmaf(dy, dy, dx * dx);
            float t  = d2 * cc[k];             // t <= 0, includes log2e
            float e;
            asm("ex2.approx.ftz.f32 %0, %1;" : "=f"(e) : "f"(t));  // 1 MUFU
            oks += e;
        }
        float cls = s_cls[nb][cid];
        // C = l1/(2K) + 100*cls - (10/K)*oks_sum
        out[(size_t)n * G + g] =
            fmaf(l1, 1.0f / 34.0f, fmaf(cls, 100.0f, oks * (-10.0f / 17.0f)));

        __syncthreads();   // buffer handoff: one barrier per n
        buf ^= 1;
    }
}

extern "C" void kernel_launch(void* const* d_in, const int* in_sizes, int n_in,
                              void* d_out, int out_size) {
    const float* logits = (const float*)d_in[0];   // [bs, nq, 2]
    const float* pkpt   = (const float*)d_in[1];   // [bs, nq, 2K]
    const int*   tids   = (const int*)d_in[2];     // [G] int32
    const float* areas  = (const float*)d_in[3];   // [G]
    const float* gkpt   = (const float*)d_in[4];   // [G, 3K]
    float*       out    = (float*)d_out;           // [bs, nq, G]

    int N = in_sizes[1] / (2 * KPT);   // 14400
    int G = in_sizes[2];               // 256

    const int rows_per_block = 16;
    int grid = (N + rows_per_block - 1) / rows_per_block;  // 900

    matcher_kernel<<<grid, G>>>(logits, pkpt, tids, areas, gkpt, out,
                                N, G, rows_per_block);
}

// round 3
// speedup vs baseline: 1.2853x; 1.2853x over previous
#include <cuda_runtime.h>

#define KPT 17
#define RCHUNK 4
#define LOG2E 1.4426950408889634f

// cc[k] = -LOG2E / (2 * var_k * area), var_k = (2*sigma_k)^2, sigma_k = S_k/10
#define CB(s) (-12.5f * LOG2E / ((s) * (s)))
__constant__ float c_cbase[KPT] = {
    CB(0.26f), CB(0.25f), CB(0.25f), CB(0.35f), CB(0.35f),
    CB(0.79f), CB(0.79f), CB(0.72f), CB(0.72f),
    CB(0.62f), CB(0.62f), CB(1.07f), CB(1.07f),
    CB(0.87f), CB(0.87f), CB(0.89f), CB(0.89f)
};

__device__ __forceinline__ float cls_cost_for(const float* __restrict__ logits,
                                              int n, int c) {
    float a = logits[2 * n + 0];
    float b = logits[2 * n + 1];
    float m = fmaxf(a, b);
    float e0 = expf(a - m), e1 = expf(b - m);
    float p = ((c == 0) ? e0 : e1) / (e0 + e1);
    float omp = 1.0f - p;
    float pos = -logf(p + 1e-12f) * 0.25f * omp * omp;
    float neg = -logf(omp + 1e-12f) * 0.75f * p * p;
    return pos - neg;
}

extern "C" __global__ void __launch_bounds__(256, 3)
matcher_kernel(const float* __restrict__ logits,   // [N, 2]
               const float* __restrict__ pkpt,     // [N, 2*K]
               const int* __restrict__ tids,       // [G] int32
               const float* __restrict__ areas,    // [G]
               const float* __restrict__ gkpt,     // [G, 3*K]
               float* __restrict__ out,            // [N, G]
               int N, int G, int rows_per_block)
{
    const int g   = threadIdx.x;     // one target per thread, blockDim.x == G
    const int tid = threadIdx.x;

    __shared__ float s_pred[2][RCHUNK][2 * KPT];
    __shared__ float s_cls[2][RCHUNK][2];

    // per-thread (per-target) constants, in registers for the whole block
    float gx[KPT], gy[KPT], cc[KPT];
    float inv_area = 1.0f / areas[g];
    int   cid = tids[g];
    cid = (cid < 0) ? 0 : ((cid > 1) ? 1 : cid);
    #pragma unroll
    for (int k = 0; k < KPT; ++k) {
        gx[k] = gkpt[g * 3 * KPT + 3 * k + 0];
        gy[k] = gkpt[g * 3 * KPT + 3 * k + 1];
        cc[k] = c_cbase[k] * inv_area;
    }

    const int ns = blockIdx.x * rows_per_block;
    const int ne = min(ns + rows_per_block, N);
    if (ns >= N) return;

    // --- preload chunk 0 into buffer 0 ---
    if (tid < RCHUNK * 2 * KPT) {
        int r = tid / (2 * KPT), j = tid % (2 * KPT);
        int row = ns + r;
        if (row < N) s_pred[0][r][j] = pkpt[row * 2 * KPT + j];
    }
    if (tid >= 192 && tid < 192 + 2 * RCHUNK) {
        int u = tid - 192, r = u >> 1, c = u & 1;
        int row = ns + r;
        if (row < N) s_cls[0][r][c] = cls_cost_for(logits, row, c);
    }
    __syncthreads();

    int buf = 0;
    for (int base = ns; base < ne; base += RCHUNK) {
        // prefetch next chunk into the other buffer
        const int nb = base + RCHUNK;
        if (nb < ne) {
            const int wb = buf ^ 1;
            if (tid < RCHUNK * 2 * KPT) {
                int r = tid / (2 * KPT), j = tid % (2 * KPT);
                int row = nb + r;
                if (row < N) s_pred[wb][r][j] = pkpt[row * 2 * KPT + j];
            }
            if (tid >= 192 && tid < 192 + 2 * RCHUNK) {
                int u = tid - 192, r = u >> 1, c = u & 1;
                int row = nb + r;
                if (row < N) s_cls[wb][r][c] = cls_cost_for(logits, row, c);
            }
        }

        // compute RCHUNK rows with independent accumulator chains (4x ILP)
        float l1[RCHUNK], ok[RCHUNK];
        #pragma unroll
        for (int r = 0; r < RCHUNK; ++r) { l1[r] = 0.0f; ok[r] = 0.0f; }

        #pragma unroll
        for (int k = 0; k < KPT; ++k) {
            #pragma unroll
            for (int r = 0; r < RCHUNK; ++r) {
                float px = s_pred[buf][r][2 * k];       // LDS broadcast
                float py = s_pred[buf][r][2 * k + 1];
                float dx = px - gx[k];
                float dy = py - gy[k];
                l1[r] += fabsf(dx);
                l1[r] += fabsf(dy);
                float t2 = fmaf(dy, dy, dx * dx) * cc[k];
                float e;
                asm("ex2.approx.ftz.f32 %0, %1;" : "=f"(e) : "f"(t2));
                ok[r] += e;
            }
        }

        #pragma unroll
        for (int r = 0; r < RCHUNK; ++r) {
            int row = base + r;
            if (row < ne) {
                float cls = s_cls[buf][r][cid];
                out[(size_t)row * G + g] =
                    fmaf(l1[r], 1.0f / 34.0f,
                         fmaf(cls, 100.0f, ok[r] * (-10.0f / 17.0f)));
            }
        }

        __syncthreads();   // one barrier per RCHUNK rows
        buf ^= 1;
    }
}

extern "C" void kernel_launch(void* const* d_in, const int* in_sizes, int n_in,
                              void* d_out, int out_size) {
    const float* logits = (const float*)d_in[0];   // [bs, nq, 2]
    const float* pkpt   = (const float*)d_in[1];   // [bs, nq, 2K]
    const int*   tids   = (const int*)d_in[2];     // [G] int32
    const float* areas  = (const float*)d_in[3];   // [G]
    const float* gkpt   = (const float*)d_in[4];   // [G, 3K]
    float*       out    = (float*)d_out;           // [bs, nq, G]

    int N = in_sizes[1] / (2 * KPT);   // 14400
    int G = in_sizes[2];               // 256

    // single balanced wave: 3 blocks/SM * ~148 SMs = ~444 resident blocks
    const int rows_per_block = 33;                       // grid = 437
    int grid = (N + rows_per_block - 1) / rows_per_block;

    matcher_kernel<<<grid, G>>>(logits, pkpt, tids, areas, gkpt, out,
                                N, G, rows_per_block);
}

// round 4
// speedup vs baseline: 1.3571x; 1.0559x over previous
#include <cuda_runtime.h>

#define KPT 17
#define RCHUNK 5
#define LOG2E 1.4426950408889634f

// cbase[k] = -LOG2E / (2 * var_k), var_k = (2*sigma_k)^2, sigma_k = S_k/10
#define CB(s) (-12.5f * LOG2E / ((s) * (s)))
__constant__ float c_cbase[KPT] = {
    CB(0.26f), CB(0.25f), CB(0.25f), CB(0.35f), CB(0.35f),
    CB(0.79f), CB(0.79f), CB(0.72f), CB(0.72f),
    CB(0.62f), CB(0.62f), CB(1.07f), CB(1.07f),
    CB(0.87f), CB(0.87f), CB(0.89f), CB(0.89f)
};

__device__ __forceinline__ float cls_cost_for(const float* __restrict__ logits,
                                              int n, int c) {
    float a = logits[2 * n + 0];
    float b = logits[2 * n + 1];
    float m = fmaxf(a, b);
    float e0 = expf(a - m), e1 = expf(b - m);
    float p = ((c == 0) ? e0 : e1) / (e0 + e1);
    float omp = 1.0f - p;
    float pos = -logf(p + 1e-12f) * 0.25f * omp * omp;
    float neg = -logf(omp + 1e-12f) * 0.75f * p * p;
    return pos - neg;
}

extern "C" __global__ void __launch_bounds__(256, 4)
matcher_kernel(const float* __restrict__ logits,   // [N, 2]
               const float* __restrict__ pkpt,     // [N, 2*K]
               const int* __restrict__ tids,       // [G] int32
               const float* __restrict__ areas,    // [G]
               const float* __restrict__ gkpt,     // [G, 3*K]
               float* __restrict__ out,            // [N, G]
               int N, int G, int rows_per_block)
{
    const int g   = threadIdx.x;     // one target per thread, blockDim.x == G
    const int tid = threadIdx.x;

    __shared__ float2 s_pred[2][RCHUNK][KPT];   // LDS.64 per (r,k)
    __shared__ float  s_cls[2][RCHUNK][2];
    __shared__ float  s_cc[KPT][256];           // [k][g]: conflict-free per-warp

    // per-thread (per-target) keypoints in registers; cc in shared
    float gx[KPT], gy[KPT];
    {
        float inv_area = 1.0f / areas[g];
        #pragma unroll
        for (int k = 0; k < KPT; ++k) {
            gx[k] = gkpt[g * 3 * KPT + 3 * k + 0];
            gy[k] = gkpt[g * 3 * KPT + 3 * k + 1];
            s_cc[k][g] = c_cbase[k] * inv_area;
        }
    }
    int cid = tids[g];
    cid = (cid < 0) ? 0 : ((cid > 1) ? 1 : cid);

    const int ns = blockIdx.x * rows_per_block;
    const int ne = min(ns + rows_per_block, N);
    if (ns >= N) return;

    // preload chunk 0 into buffer 0
    if (tid < RCHUNK * 2 * KPT) {
        int r = tid / (2 * KPT), j = tid % (2 * KPT);
        int row = ns + r;
        if (row < N)
            ((float*)&s_pred[0][r][0])[j] = pkpt[row * 2 * KPT + j];
    }
    if (tid >= 192 && tid < 192 + 2 * RCHUNK) {
        int u = tid - 192, r = u >> 1, c = u & 1;
        int row = ns + r;
        if (row < N) s_cls[0][r][c] = cls_cost_for(logits, row, c);
    }
    __syncthreads();

    int buf = 0;
    for (int base = ns; base < ne; base += RCHUNK) {
        // prefetch next chunk into the other buffer
        const int nb = base + RCHUNK;
        if (nb < ne) {
            const int wb = buf ^ 1;
            if (tid < RCHUNK * 2 * KPT) {
                int r = tid / (2 * KPT), j = tid % (2 * KPT);
                int row = nb + r;
                if (row < N)
                    ((float*)&s_pred[wb][r][0])[j] = pkpt[row * 2 * KPT + j];
            }
            if (tid >= 192 && tid < 192 + 2 * RCHUNK) {
                int u = tid - 192, r = u >> 1, c = u & 1;
                int row = nb + r;
                if (row < N) s_cls[wb][r][c] = cls_cost_for(logits, row, c);
            }
        }

        float l1[RCHUNK], ok[RCHUNK];
        #pragma unroll
        for (int r = 0; r < RCHUNK; ++r) { l1[r] = 0.0f; ok[r] = 0.0f; }

        #pragma unroll
        for (int k = 0; k < KPT; ++k) {
            const float cck = s_cc[k][g];
            #pragma unroll
            for (int r = 0; r < RCHUNK; ++r) {
                float2 p = s_pred[buf][r][k];   // one LDS.64 broadcast
                float dx = p.x - gx[k];
                float dy = p.y - gy[k];
                l1[r] += fabsf(dx);
                l1[r] += fabsf(dy);
                float t2 = fmaf(dy, dy, dx * dx) * cck;
                float e;
                asm("ex2.approx.ftz.f32 %0, %1;" : "=f"(e) : "f"(t2));
                ok[r] += e;
            }
        }

        #pragma unroll
        for (int r = 0; r < RCHUNK; ++r) {
            int row = base + r;
            if (row < ne) {
                float cls = s_cls[buf][r][cid];
                out[(size_t)row * G + g] =
                    fmaf(l1[r], 1.0f / 34.0f,
                         fmaf(cls, 100.0f, ok[r] * (-10.0f / 17.0f)));
            }
        }

        __syncthreads();   // one barrier per RCHUNK rows
        buf ^= 1;
    }
}

extern "C" void kernel_launch(void* const* d_in, const int* in_sizes, int n_in,
                              void* d_out, int out_size) {
    const float* logits = (const float*)d_in[0];   // [bs, nq, 2]
    const float* pkpt   = (const float*)d_in[1];   // [bs, nq, 2K]
    const int*   tids   = (const int*)d_in[2];     // [G] int32
    const float* areas  = (const float*)d_in[3];   // [G]
    const float* gkpt   = (const float*)d_in[4];   // [G, 3K]
    float*       out    = (float*)d_out;           // [bs, nq, G]

    int N = in_sizes[1] / (2 * KPT);   // 14400
    int G = in_sizes[2];               // 256

    // 4 blocks/SM * 148 SMs = 592 resident; grid 576 = single balanced wave,
    // and 25 rows = exactly 5 chunks of RCHUNK=5 (no padded-chunk waste)
    const int rows_per_block = 25;
    int grid = (N + rows_per_block - 1) / rows_per_block;  // 576

    matcher_kernel<<<grid, G>>>(logits, pkpt, tids, areas, gkpt, out,
                                N, G, rows_per_block);
}